// round 13
// baseline (speedup 1.0000x reference)
#include <cuda_runtime.h>
#include <cuda_bf16.h>
#include <cstdint>

// Problem shape (fixed by dataset)
#define N_MAX   50000
#define E_MAX   800000
#define EMB     128
#define KTOT    256     // NF + EMB

// ---------------- device scratch (static: no runtime allocation) -----------
__device__ int      g_deg[N_MAX];
__device__ int      g_off[N_MAX + 1];
__device__ int      g_rank[E_MAX];
__device__ int      g_eidx[E_MAX];
// aggr in fragment-major order: per node 128 words =
// [chunk(2)][s(4)][tig(4)][split*2+khalf(4)]
__device__ uint32_t g_Af[N_MAX * 128];
// W in fragment-major order: per out-col 256 words =
// [S(16)][tig(4)][split*2+khalf(4)]
__device__ uint32_t g_Wf[EMB * 256];

// ===================== bf16 split helpers ==================================
__device__ __forceinline__ uint32_t pk_bf2(float lo, float hi) {
    uint32_t r;
    asm("cvt.rn.bf16x2.f32 %0, %1, %2;" : "=r"(r) : "f"(hi), "f"(lo));
    return r;
}
__device__ __forceinline__ float2 unpk_bf2(uint32_t w) {
    __nv_bfloat162 b = *reinterpret_cast<__nv_bfloat162*>(&w);
    return __bfloat1622float2(b);
}
__device__ __forceinline__ void split2(float a, float b,
                                       uint32_t& hi, uint32_t& lo) {
    hi = pk_bf2(a, b);
    float2 f = unpk_bf2(hi);
    lo = pk_bf2(a - f.x, b - f.y);
}

// ============== prep: zero deg + W f32 -> fragment-major bf16 hi/lo ========
__global__ void prep_kernel(const float2* __restrict__ W2, int n) {
    int i = blockIdx.x * blockDim.x + threadIdx.x;
    if (i < n) g_deg[i] = 0;
    if (i < EMB * (KTOT / 2)) {             // 16384 k-pairs
        int c = i >> 7;                     // out col
        int p = i & 127;                    // k-pair
        float2 v = W2[i];                   // W[c][2p..2p+1]
        uint32_t hi, lo;
        split2(v.x, v.y, hi, lo);
        int w = (p >> 3) * 16 + (p & 3) * 4 + ((p >> 2) & 1);
        g_Wf[c * 256 + w]     = hi;         // split 0
        g_Wf[c * 256 + w + 2] = lo;         // split 1
    }
}

// ============================ CSR build ====================================
__global__ void hist_rank_kernel(const int* __restrict__ dst, int e) {
    int i = blockIdx.x * blockDim.x + threadIdx.x;
    if (i < e) g_rank[i] = atomicAdd(&g_deg[dst[i]], 1);
}

__global__ void scan_kernel(int n) {
    const int T = 1024;
    int tid  = threadIdx.x;
    int lane = tid & 31;
    int wid  = tid >> 5;
    int C = (n + T - 1) / T;
    int s = tid * C;
    int e = min(s + C, n);

    int sum = 0;
    for (int i = s; i < e; i++) sum += g_deg[i];

    int v = sum;
    #pragma unroll
    for (int d = 1; d < 32; d <<= 1) {
        int t = __shfl_up_sync(0xffffffffu, v, d);
        if (lane >= d) v += t;
    }
    __shared__ int wsum[32];
    if (lane == 31) wsum[wid] = v;
    __syncthreads();
    if (wid == 0) {
        int w = wsum[lane];
        #pragma unroll
        for (int d = 1; d < 32; d <<= 1) {
            int t = __shfl_up_sync(0xffffffffu, w, d);
            if (lane >= d) w += t;
        }
        wsum[lane] = w;
    }
    __syncthreads();

    int excl = (v - sum) + (wid > 0 ? wsum[wid - 1] : 0);
    int run = excl;
    for (int i = s; i < e; i++) {
        g_off[i] = run;
        run += g_deg[i];
    }
    if (e == n) g_off[n] = run;
}

__global__ void scatter_kernel(const int* __restrict__ dst, int e) {
    int i = blockIdx.x * blockDim.x + threadIdx.x;
    if (i < e) g_eidx[g_off[dst[i]] + g_rank[i]] = i;
}

// --------------------------- gather kernel ---------------------------------
// One warp per node, 16B per lane, unroll 8 for MLP. Output written in
// fragment-major bf16 hi/lo order (GEMM stages it with straight uint4 copy).
__global__ void __launch_bounds__(256)
gather_kernel(const float4* __restrict__ h4, int n) {
    int node = blockIdx.x * 8 + (threadIdx.x >> 5);
    int lane = threadIdx.x & 31;
    if (node >= n) return;

    int s = g_off[node];
    int e = g_off[node + 1];
    float4 a = make_float4(0.f, 0.f, 0.f, 0.f);
    int j = s;
    for (; j + 8 <= e; j += 8) {
        float4 v[8];
        #pragma unroll
        for (int u = 0; u < 8; u++) {
            int ei = __ldg(g_eidx + j + u);
            v[u] = __ldg(h4 + (size_t)ei * 32 + lane);
        }
        #pragma unroll
        for (int u = 0; u < 8; u++) {
            a.x += v[u].x; a.y += v[u].y; a.z += v[u].z; a.w += v[u].w;
        }
    }
    if (j + 4 <= e) {
        float4 v[4];
        #pragma unroll
        for (int u = 0; u < 4; u++) {
            int ei = __ldg(g_eidx + j + u);
            v[u] = __ldg(h4 + (size_t)ei * 32 + lane);
        }
        #pragma unroll
        for (int u = 0; u < 4; u++) {
            a.x += v[u].x; a.y += v[u].y; a.z += v[u].z; a.w += v[u].w;
        }
        j += 4;
    }
    for (; j < e; j++) {
        int ei = __ldg(g_eidx + j);
        float4 v0 = __ldg(h4 + (size_t)ei * 32 + lane);
        a.x += v0.x; a.y += v0.y; a.z += v0.z; a.w += v0.w;
    }

    // fragment-major store: pairs p0 = 2*lane, p1 = 2*lane+1 (k = 4*lane..+3)
    uint32_t h0, l0, h1, l1;
    split2(a.x, a.y, h0, l0);
    split2(a.z, a.w, h1, l1);
    size_t base = (size_t)node * 128;
    int p0    = 2 * lane;
    int chunk = p0 >> 5;
    int pp    = p0 & 31;
    int w0 = chunk * 64 + (pp >> 3) * 16 + (pp & 3) * 4 + ((pp >> 2) & 1);
    int w1 = w0 + 4;                        // pair p0+1: tig+1
    g_Af[base + w0]     = h0;
    g_Af[base + w0 + 2] = l0;
    g_Af[base + w1]     = h1;
    g_Af[base + w1 + 2] = l1;
}

// ===================== HMMA GEMM: out = relu(q @ W^T + b) ==================
// CTA = 128 nodes x 128 cols, 512 threads (16 warps: 4m x 4n, warp 32x32).
// K=256 in 4 chunks of 64. Fragment-major smem: per (row, k16 step s, tig)
// the 4 words {hi_k0, hi_k8, lo_k0, lo_k8} are one aligned LDS.128.
// Row stride 80 words -> phase-conflict-free (validated R12).
// Split-precision: D += Ah*Wh + Ah*Wl + Al*Wh (fp32 accum).
// vs R12: GM 64->128 halves W stagings + syncs per node; warp residency
// unchanged (1x512 vs 2x256). No occupancy cap (R9/R11 lesson).

#define GM       128
#define GTHREADS 512
#define RW       80
#define SA_W     (GM * RW)                 // 10240 words
#define SW_W     (EMB * RW)                // 10240 words
#define GSMEM_W  (SA_W + SW_W + EMB)
#define GSMEM_B  (GSMEM_W * 4)             // 82432 B

__device__ __forceinline__ void mma_bf16(float4& d,
    uint32_t a0, uint32_t a1, uint32_t a2, uint32_t a3,
    uint32_t b0, uint32_t b1) {
    asm("mma.sync.aligned.m16n8k16.row.col.f32.bf16.bf16.f32 "
        "{%0,%1,%2,%3}, {%4,%5,%6,%7}, {%8,%9}, {%0,%1,%2,%3};"
        : "+f"(d.x), "+f"(d.y), "+f"(d.z), "+f"(d.w)
        : "r"(a0), "r"(a1), "r"(a2), "r"(a3), "r"(b0), "r"(b1));
}

__global__ void __launch_bounds__(GTHREADS)
gemm_kernel(const float4* __restrict__ x4,
            const float*  __restrict__ bias,
            float* __restrict__ out, int n) {
    extern __shared__ uint32_t sm[];
    uint32_t* sA = sm;                     // [128][80]
    uint32_t* sW = sm + SA_W;              // [128][80]
    float*    sB = reinterpret_cast<float*>(sm + SA_W + SW_W);

    int tid  = threadIdx.x;
    int warp = tid >> 5;
    int lane = tid & 31;
    int g    = lane >> 2;
    int tig  = lane & 3;
    int mw   = warp >> 2;                  // 0..3
    int nw   = warp & 3;                   // 0..3
    int m0   = mw * 32;
    int n0   = nw * 32;
    int nb   = blockIdx.x * GM;

    if (tid < EMB) sB[tid] = bias[tid];

    float4 acc[2][4];
    #pragma unroll
    for (int mt = 0; mt < 2; mt++)
        #pragma unroll
        for (int nt = 0; nt < 4; nt++)
            acc[mt][nt] = make_float4(0.f, 0.f, 0.f, 0.f);

    for (int kc = 0; kc < KTOT; kc += 64) {
        __syncthreads();
        if (kc < 128) {
            // ---- stage A from x: f32 -> bf16 hi/lo, fragment scatter ----
            #pragma unroll
            for (int f = tid; f < GM * 16; f += GTHREADS) {
                int m = f >> 4;
                int q = f & 15;             // float4 = pairs 2q, 2q+1
                int node = nb + m;
                float4 v = make_float4(0.f, 0.f, 0.f, 0.f);
                if (node < n) v = x4[(size_t)node * 32 + (kc >> 2) + q];
                uint32_t h0, l0, h1, l1;
                split2(v.x, v.y, h0, l0);
                split2(v.z, v.w, h1, l1);
                int p0 = 2 * q;
                int w0 = (p0 >> 3) * 16 + (p0 & 3) * 4 + ((p0 >> 2) & 1);
                int rb = m * RW;
                sA[rb + w0]         = h0;
                sA[rb + w0 + 2]     = l0;
                sA[rb + w0 + 4]     = h1;   // pair p0+1: tig+1
                sA[rb + w0 + 6]     = l1;
            }
        } else {
            // ---- stage A from pre-split fragment-major aggr: copy ----
            int cb = (kc - 128);            // 0 or 64: word base in g_Af
            #pragma unroll
            for (int f = tid; f < GM * 16; f += GTHREADS) {
                int m = f >> 4;
                int i = f & 15;
                int node = nb + m;
                uint4 v = make_uint4(0u, 0u, 0u, 0u);
                if (node < n)
                    v = *reinterpret_cast<const uint4*>(
                        g_Af + (size_t)node * 128 + cb + i * 4);
                *reinterpret_cast<uint4*>(sA + m * RW + i * 4) = v;
            }
        }
        // ---- stage W: straight copy of fragment-major columns ----
        #pragma unroll
        for (int f = tid; f < EMB * 16; f += GTHREADS) {
            int c = f >> 4;
            int i = f & 15;
            *reinterpret_cast<uint4*>(sW + c * RW + i * 4) =
                *reinterpret_cast<const uint4*>(g_Wf + c * 256 + kc + i * 4);
        }
        __syncthreads();

        // ---- 4 k16 steps, 8 LDS.128 each ----
        #pragma unroll
        for (int s = 0; s < 4; s++) {
            int wb = s * 16 + tig * 4;

            uint4 A0[2], A1[2];             // {h_k0, h_k8, l_k0, l_k8}
            #pragma unroll
            for (int mt = 0; mt < 2; mt++) {
                int r0 = (m0 + mt * 16 + g) * RW + wb;
                A0[mt] = *reinterpret_cast<const uint4*>(sA + r0);
                A1[mt] = *reinterpret_cast<const uint4*>(sA + r0 + 8 * RW);
            }
            uint4 B[4];                     // {bh0, bh1, bl0, bl1}
            #pragma unroll
            for (int nt = 0; nt < 4; nt++) {
                int rn = (n0 + nt * 8 + g) * RW + wb;
                B[nt] = *reinterpret_cast<const uint4*>(sW + rn);
            }
            #pragma unroll
            for (int mt = 0; mt < 2; mt++)
                #pragma unroll
                for (int nt = 0; nt < 4; nt++) {
                    mma_bf16(acc[mt][nt],
                             A0[mt].x, A1[mt].x, A0[mt].y, A1[mt].y,
                             B[nt].x, B[nt].y);
                    mma_bf16(acc[mt][nt],
                             A0[mt].x, A1[mt].x, A0[mt].y, A1[mt].y,
                             B[nt].z, B[nt].w);
                    mma_bf16(acc[mt][nt],
                             A0[mt].z, A1[mt].z, A0[mt].w, A1[mt].w,
                             B[nt].x, B[nt].y);
                }
        }
    }

    // ---- epilogue: bias + relu + store ----
    #pragma unroll
    for (int mt = 0; mt < 2; mt++) {
        int r0 = nb + m0 + mt * 16 + g;
        int r1 = r0 + 8;
        #pragma unroll
        for (int nt = 0; nt < 4; nt++) {
            int col = n0 + nt * 8 + tig * 2;
            float bx = sB[col], by = sB[col + 1];
            float4 a = acc[mt][nt];
            if (r0 < n) {
                float2 v = make_float2(fmaxf(a.x + bx, 0.f),
                                       fmaxf(a.y + by, 0.f));
                *reinterpret_cast<float2*>(out + (size_t)r0 * EMB + col) = v;
            }
            if (r1 < n) {
                float2 v = make_float2(fmaxf(a.z + bx, 0.f),
                                       fmaxf(a.w + by, 0.f));
                *reinterpret_cast<float2*>(out + (size_t)r1 * EMB + col) = v;
            }
        }
    }
}

// ---------------- launch ----------------------------------------------------
extern "C" void kernel_launch(void* const* d_in, const int* in_sizes, int n_in,
                              void* d_out, int out_size) {
    const float* h        = (const float*)d_in[0];   // [E, 128]
    const float* x        = (const float*)d_in[1];   // [N, 128]
    const int*   edge_dst = (const int*)  d_in[2];   // [E] int32
    const float* W        = (const float*)d_in[3];   // [128, 256]
    const float* b        = (const float*)d_in[4];   // [128]
    float*       out      = (float*)d_out;           // [N, 128]

    int E = in_sizes[2];
    int N = in_sizes[1] / EMB;

    cudaFuncSetAttribute(gemm_kernel,
                         cudaFuncAttributeMaxDynamicSharedMemorySize, GSMEM_B);

    int prepN = (N > EMB * (KTOT / 2)) ? N : EMB * (KTOT / 2);

    prep_kernel<<<(prepN + 255) / 256, 256>>>(
        reinterpret_cast<const float2*>(W), N);
    hist_rank_kernel<<<(E + 255) / 256, 256>>>(edge_dst, E);
    scan_kernel<<<1, 1024>>>(N);
    scatter_kernel<<<(E + 255) / 256, 256>>>(edge_dst, E);
    gather_kernel<<<(N + 7) / 8, 256>>>(
        reinterpret_cast<const float4*>(h), N);
    gemm_kernel<<<(N + GM - 1) / GM, GTHREADS, GSMEM_B>>>(
        reinterpret_cast<const float4*>(x), b, out, N);
}

// round 15
// speedup vs baseline: 1.0528x; 1.0528x over previous
#include <cuda_runtime.h>
#include <cuda_bf16.h>
#include <cstdint>

// Problem shape (fixed by dataset)
#define N_MAX   50000
#define E_MAX   800000
#define EMB     128
#define KTOT    256     // NF + EMB

// ---------------- device scratch (static: no runtime allocation) -----------
__device__ int      g_deg[N_MAX];
__device__ int      g_off[N_MAX + 1];
__device__ int      g_rank[E_MAX];
__device__ int      g_eidx[E_MAX];
// aggr in fragment-major order: per node 128 words =
// [chunk(2)][s(4)][tig(4)][split*2+khalf(4)]
// padded by 64 nodes so the last CTA's cp.async copies can read unguarded
__device__ uint32_t g_Af[(N_MAX + 64) * 128];
// W in fragment-major order: per out-col 256 words =
// [S(16)][tig(4)][split*2+khalf(4)]
__device__ uint32_t g_Wf[EMB * 256];

// ===================== bf16 split helpers ==================================
__device__ __forceinline__ uint32_t pk_bf2(float lo, float hi) {
    uint32_t r;
    asm("cvt.rn.bf16x2.f32 %0, %1, %2;" : "=r"(r) : "f"(hi), "f"(lo));
    return r;
}
__device__ __forceinline__ float2 unpk_bf2(uint32_t w) {
    __nv_bfloat162 b = *reinterpret_cast<__nv_bfloat162*>(&w);
    return __bfloat1622float2(b);
}
__device__ __forceinline__ void split2(float a, float b,
                                       uint32_t& hi, uint32_t& lo) {
    hi = pk_bf2(a, b);
    float2 f = unpk_bf2(hi);
    lo = pk_bf2(a - f.x, b - f.y);
}

// ===================== cp.async helpers ====================================
__device__ __forceinline__ void cp16(uint32_t saddr, const void* gaddr) {
    asm volatile("cp.async.cg.shared.global [%0], [%1], 16;"
                 :: "r"(saddr), "l"(gaddr) : "memory");
}
#define CP_COMMIT() asm volatile("cp.async.commit_group;" ::: "memory")
#define CP_WAIT0()  asm volatile("cp.async.wait_group 0;" ::: "memory")

// ============== prep: zero deg + W f32 -> fragment-major bf16 hi/lo ========
__global__ void prep_kernel(const float2* __restrict__ W2, int n) {
    int i = blockIdx.x * blockDim.x + threadIdx.x;
    if (i < n) g_deg[i] = 0;
    if (i < EMB * (KTOT / 2)) {             // 16384 k-pairs
        int c = i >> 7;                     // out col
        int p = i & 127;                    // k-pair
        float2 v = W2[i];                   // W[c][2p..2p+1]
        uint32_t hi, lo;
        split2(v.x, v.y, hi, lo);
        int w = (p >> 3) * 16 + (p & 3) * 4 + ((p >> 2) & 1);
        g_Wf[c * 256 + w]     = hi;         // split 0
        g_Wf[c * 256 + w + 2] = lo;         // split 1
    }
}

// ============================ CSR build ====================================
__global__ void hist_rank_kernel(const int* __restrict__ dst, int e) {
    int i = blockIdx.x * blockDim.x + threadIdx.x;
    if (i < e) g_rank[i] = atomicAdd(&g_deg[dst[i]], 1);
}

__global__ void scan_kernel(int n) {
    const int T = 1024;
    int tid  = threadIdx.x;
    int lane = tid & 31;
    int wid  = tid >> 5;
    int C = (n + T - 1) / T;
    int s = tid * C;
    int e = min(s + C, n);

    int sum = 0;
    for (int i = s; i < e; i++) sum += g_deg[i];

    int v = sum;
    #pragma unroll
    for (int d = 1; d < 32; d <<= 1) {
        int t = __shfl_up_sync(0xffffffffu, v, d);
        if (lane >= d) v += t;
    }
    __shared__ int wsum[32];
    if (lane == 31) wsum[wid] = v;
    __syncthreads();
    if (wid == 0) {
        int w = wsum[lane];
        #pragma unroll
        for (int d = 1; d < 32; d <<= 1) {
            int t = __shfl_up_sync(0xffffffffu, w, d);
            if (lane >= d) w += t;
        }
        wsum[lane] = w;
    }
    __syncthreads();

    int excl = (v - sum) + (wid > 0 ? wsum[wid - 1] : 0);
    int run = excl;
    for (int i = s; i < e; i++) {
        g_off[i] = run;
        run += g_deg[i];
    }
    if (e == n) g_off[n] = run;
}

__global__ void scatter_kernel(const int* __restrict__ dst, int e) {
    int i = blockIdx.x * blockDim.x + threadIdx.x;
    if (i < e) g_eidx[g_off[dst[i]] + g_rank[i]] = i;
}

// --------------------------- gather kernel ---------------------------------
// One warp per node, 16B per lane, unroll 8 for MLP. Output written in
// fragment-major bf16 hi/lo order (GEMM stages it with straight cp.async).
__global__ void __launch_bounds__(256)
gather_kernel(const float4* __restrict__ h4, int n) {
    int node = blockIdx.x * 8 + (threadIdx.x >> 5);
    int lane = threadIdx.x & 31;
    if (node >= n) return;

    int s = g_off[node];
    int e = g_off[node + 1];
    float4 a = make_float4(0.f, 0.f, 0.f, 0.f);
    int j = s;
    for (; j + 8 <= e; j += 8) {
        float4 v[8];
        #pragma unroll
        for (int u = 0; u < 8; u++) {
            int ei = __ldg(g_eidx + j + u);
            v[u] = __ldg(h4 + (size_t)ei * 32 + lane);
        }
        #pragma unroll
        for (int u = 0; u < 8; u++) {
            a.x += v[u].x; a.y += v[u].y; a.z += v[u].z; a.w += v[u].w;
        }
    }
    if (j + 4 <= e) {
        float4 v[4];
        #pragma unroll
        for (int u = 0; u < 4; u++) {
            int ei = __ldg(g_eidx + j + u);
            v[u] = __ldg(h4 + (size_t)ei * 32 + lane);
        }
        #pragma unroll
        for (int u = 0; u < 4; u++) {
            a.x += v[u].x; a.y += v[u].y; a.z += v[u].z; a.w += v[u].w;
        }
        j += 4;
    }
    for (; j < e; j++) {
        int ei = __ldg(g_eidx + j);
        float4 v0 = __ldg(h4 + (size_t)ei * 32 + lane);
        a.x += v0.x; a.y += v0.y; a.z += v0.z; a.w += v0.w;
    }

    // fragment-major store: pairs p0 = 2*lane, p1 = 2*lane+1 (k = 4*lane..+3)
    uint32_t h0, l0, h1, l1;
    split2(a.x, a.y, h0, l0);
    split2(a.z, a.w, h1, l1);
    size_t base = (size_t)node * 128;
    int p0    = 2 * lane;
    int chunk = p0 >> 5;
    int pp    = p0 & 31;
    int w0 = chunk * 64 + (pp >> 3) * 16 + (pp & 3) * 4 + ((pp >> 2) & 1);
    int w1 = w0 + 4;                        // pair p0+1: tig+1
    g_Af[base + w0]     = h0;
    g_Af[base + w0 + 2] = l0;
    g_Af[base + w1]     = h1;
    g_Af[base + w1 + 2] = l1;
}

// ===================== HMMA GEMM: out = relu(q @ W^T + b) ==================
// CTA = 64 nodes x 128 cols, 256 threads (8 warps: 2m x 4n, warp 32x32).
// K=256 in 4 chunks of 64. Fragment-major smem: per (row, k16 step s, tig)
// the 4 words {hi_k0, hi_k8, lo_k0, lo_k8} are one aligned LDS.128.
// Row stride 80 words -> phase-conflict-free (validated R12).
// W chunks and aggr-A chunks staged via cp.async (no reg round trip,
// overlapped with the x-half split2 conversion). 2 CTAs/SM (R12 shape).
// Split-precision: D += Ah*Wh + Ah*Wl + Al*Wh (fp32 accum).

#define GM       64
#define RW       80
#define SA_W     (GM * RW)                 // 5120 words
#define SW_W     (EMB * RW)                // 10240 words
#define GSMEM_W  (SA_W + SW_W + EMB)
#define GSMEM_B  (GSMEM_W * 4)             // 61952 B

__device__ __forceinline__ void mma_bf16(float4& d,
    uint32_t a0, uint32_t a1, uint32_t a2, uint32_t a3,
    uint32_t b0, uint32_t b1) {
    asm("mma.sync.aligned.m16n8k16.row.col.f32.bf16.bf16.f32 "
        "{%0,%1,%2,%3}, {%4,%5,%6,%7}, {%8,%9}, {%0,%1,%2,%3};"
        : "+f"(d.x), "+f"(d.y), "+f"(d.z), "+f"(d.w)
        : "r"(a0), "r"(a1), "r"(a2), "r"(a3), "r"(b0), "r"(b1));
}

__global__ void __launch_bounds__(256, 2)
gemm_kernel(const float4* __restrict__ x4,
            const float*  __restrict__ bias,
            float* __restrict__ out, int n) {
    extern __shared__ uint32_t sm[];
    uint32_t* sA = sm;                     // [64][80]
    uint32_t* sW = sm + SA_W;              // [128][80]
    float*    sB = reinterpret_cast<float*>(sm + SA_W + SW_W);

    uint32_t sA_u = (uint32_t)__cvta_generic_to_shared(sA);
    uint32_t sW_u = (uint32_t)__cvta_generic_to_shared(sW);

    int tid  = threadIdx.x;
    int warp = tid >> 5;
    int lane = tid & 31;
    int g    = lane >> 2;
    int tig  = lane & 3;
    int mw   = warp >> 2;
    int nw   = warp & 3;
    int m0   = mw * 32;
    int n0   = nw * 32;
    int nb   = blockIdx.x * GM;

    if (tid < EMB) sB[tid] = bias[tid];

    float4 acc[2][4];
    #pragma unroll
    for (int mt = 0; mt < 2; mt++)
        #pragma unroll
        for (int nt = 0; nt < 4; nt++)
            acc[mt][nt] = make_float4(0.f, 0.f, 0.f, 0.f);

    for (int kc = 0; kc < KTOT; kc += 64) {
        __syncthreads();
        // ---- stage W chunk via cp.async: 2048 16B units, 8 per thread ----
        #pragma unroll
        for (int f = tid; f < EMB * 16; f += 256) {
            int c = f >> 4;
            int i = f & 15;
            cp16(sW_u + (c * RW + i * 4) * 4, g_Wf + c * 256 + kc + i * 4);
        }
        if (kc < 128) {
            CP_COMMIT();
            // ---- stage A from x: f32 -> bf16 hi/lo (overlaps cp.async) ----
            #pragma unroll
            for (int f = tid; f < GM * 16; f += 256) {
                int m = f >> 4;
                int q = f & 15;             // float4 = pairs 2q, 2q+1
                int node = nb + m;
                float4 v = make_float4(0.f, 0.f, 0.f, 0.f);
                if (node < n) v = x4[(size_t)node * 32 + (kc >> 2) + q];
                uint32_t h0, l0, h1, l1;
                split2(v.x, v.y, h0, l0);
                split2(v.z, v.w, h1, l1);
                int p0 = 2 * q;
                int w0 = (p0 >> 3) * 16 + (p0 & 3) * 4 + ((p0 >> 2) & 1);
                int rb = m * RW;
                sA[rb + w0]         = h0;
                sA[rb + w0 + 2]     = l0;
                sA[rb + w0 + 4]     = h1;   // pair p0+1: tig+1
                sA[rb + w0 + 6]     = l1;
            }
        } else {
            // ---- stage A from fragment-major aggr via cp.async ----
            // (g_Af padded past N_MAX: unguarded reads OK; rows >= n
            //  carry garbage but are never stored in the epilogue)
            int cb = (kc - 128);            // 0 or 64: word base in g_Af
            #pragma unroll
            for (int f = tid; f < GM * 16; f += 256) {
                int m = f >> 4;
                int i = f & 15;
                cp16(sA_u + (m * RW + i * 4) * 4,
                     g_Af + (size_t)(nb + m) * 128 + cb + i * 4);
            }
            CP_COMMIT();
        }
        CP_WAIT0();
        __syncthreads();

        // ---- 4 k16 steps, 8 LDS.128 each ----
        #pragma unroll
        for (int s = 0; s < 4; s++) {
            int wb = s * 16 + tig * 4;

            uint4 A0[2], A1[2];             // {h_k0, h_k8, l_k0, l_k8}
            #pragma unroll
            for (int mt = 0; mt < 2; mt++) {
                int r0 = (m0 + mt * 16 + g) * RW + wb;
                A0[mt] = *reinterpret_cast<const uint4*>(sA + r0);
                A1[mt] = *reinterpret_cast<const uint4*>(sA + r0 + 8 * RW);
            }
            uint4 B[4];                     // {bh0, bh1, bl0, bl1}
            #pragma unroll
            for (int nt = 0; nt < 4; nt++) {
                int rn = (n0 + nt * 8 + g) * RW + wb;
                B[nt] = *reinterpret_cast<const uint4*>(sW + rn);
            }
            #pragma unroll
            for (int mt = 0; mt < 2; mt++)
                #pragma unroll
                for (int nt = 0; nt < 4; nt++) {
                    mma_bf16(acc[mt][nt],
                             A0[mt].x, A1[mt].x, A0[mt].y, A1[mt].y,
                             B[nt].x, B[nt].y);
                    mma_bf16(acc[mt][nt],
                             A0[mt].x, A1[mt].x, A0[mt].y, A1[mt].y,
                             B[nt].z, B[nt].w);
                    mma_bf16(acc[mt][nt],
                             A0[mt].z, A1[mt].z, A0[mt].w, A1[mt].w,
                             B[nt].x, B[nt].y);
                }
        }
    }

    // ---- epilogue: bias + relu + store ----
    #pragma unroll
    for (int mt = 0; mt < 2; mt++) {
        int r0 = nb + m0 + mt * 16 + g;
        int r1 = r0 + 8;
        #pragma unroll
        for (int nt = 0; nt < 4; nt++) {
            int col = n0 + nt * 8 + tig * 2;
            float bx = sB[col], by = sB[col + 1];
            float4 a = acc[mt][nt];
            if (r0 < n) {
                float2 v = make_float2(fmaxf(a.x + bx, 0.f),
                                       fmaxf(a.y + by, 0.f));
                *reinterpret_cast<float2*>(out + (size_t)r0 * EMB + col) = v;
            }
            if (r1 < n) {
                float2 v = make_float2(fmaxf(a.z + bx, 0.f),
                                       fmaxf(a.w + by, 0.f));
                *reinterpret_cast<float2*>(out + (size_t)r1 * EMB + col) = v;
            }
        }
    }
}

// ---------------- launch ----------------------------------------------------
extern "C" void kernel_launch(void* const* d_in, const int* in_sizes, int n_in,
                              void* d_out, int out_size) {
    const float* h        = (const float*)d_in[0];   // [E, 128]
    const float* x        = (const float*)d_in[1];   // [N, 128]
    const int*   edge_dst = (const int*)  d_in[2];   // [E] int32
    const float* W        = (const float*)d_in[3];   // [128, 256]
    const float* b        = (const float*)d_in[4];   // [128]
    float*       out      = (float*)d_out;           // [N, 128]

    int E = in_sizes[2];
    int N = in_sizes[1] / EMB;

    cudaFuncSetAttribute(gemm_kernel,
                         cudaFuncAttributeMaxDynamicSharedMemorySize, GSMEM_B);

    int prepN = (N > EMB * (KTOT / 2)) ? N : EMB * (KTOT / 2);

    prep_kernel<<<(prepN + 255) / 256, 256>>>(
        reinterpret_cast<const float2*>(W), N);
    hist_rank_kernel<<<(E + 255) / 256, 256>>>(edge_dst, E);
    scan_kernel<<<1, 1024>>>(N);
    scatter_kernel<<<(E + 255) / 256, 256>>>(edge_dst, E);
    gather_kernel<<<(N + 7) / 8, 256>>>(
        reinterpret_cast<const float4*>(h), N);
    gemm_kernel<<<(N + GM - 1) / GM, 256, GSMEM_B>>>(
        reinterpret_cast<const float4*>(x), b, out, N);
}

// round 16
// speedup vs baseline: 1.0924x; 1.0376x over previous
#include <cuda_runtime.h>
#include <cuda_bf16.h>
#include <cstdint>

// Problem shape (fixed by dataset)
#define N_MAX   50000
#define E_MAX   800000
#define EMB     128
#define KTOT    256     // NF + EMB

// ---------------- device scratch (static: no runtime allocation) -----------
__device__ int      g_deg[N_MAX];
__device__ int      g_off[N_MAX + 1];
__device__ int      g_rank[E_MAX];
__device__ int      g_eidx[E_MAX];
// aggr in fragment-major order: per node 128 words =
// [chunk(2)][s(4)][tig(4)][split*2+khalf(4)]
// padded by 64 nodes so the last CTA's cp.async copies can read unguarded
__device__ uint32_t g_Af[(N_MAX + 64) * 128];
// W in fragment-major order: per out-col 256 words =
// [S(16)][tig(4)][split*2+khalf(4)]
__device__ uint32_t g_Wf[EMB * 256];

// ===================== bf16 split helpers ==================================
__device__ __forceinline__ uint32_t pk_bf2(float lo, float hi) {
    uint32_t r;
    asm("cvt.rn.bf16x2.f32 %0, %1, %2;" : "=r"(r) : "f"(hi), "f"(lo));
    return r;
}
__device__ __forceinline__ float2 unpk_bf2(uint32_t w) {
    __nv_bfloat162 b = *reinterpret_cast<__nv_bfloat162*>(&w);
    return __bfloat1622float2(b);
}
__device__ __forceinline__ void split2(float a, float b,
                                       uint32_t& hi, uint32_t& lo) {
    hi = pk_bf2(a, b);
    float2 f = unpk_bf2(hi);
    lo = pk_bf2(a - f.x, b - f.y);
}

// ===================== cp.async helpers ====================================
__device__ __forceinline__ void cp16(uint32_t saddr, const void* gaddr) {
    asm volatile("cp.async.cg.shared.global [%0], [%1], 16;"
                 :: "r"(saddr), "l"(gaddr) : "memory");
}
#define CP_COMMIT() asm volatile("cp.async.commit_group;" ::: "memory")
#define CP_WAIT0()  asm volatile("cp.async.wait_group 0;" ::: "memory")

// ============== prep: zero deg + W f32 -> fragment-major bf16 hi/lo ========
__global__ void prep_kernel(const float2* __restrict__ W2, int n) {
    int i = blockIdx.x * blockDim.x + threadIdx.x;
    if (i < n) g_deg[i] = 0;
    if (i < EMB * (KTOT / 2)) {             // 16384 k-pairs
        int c = i >> 7;                     // out col
        int p = i & 127;                    // k-pair
        float2 v = W2[i];                   // W[c][2p..2p+1]
        uint32_t hi, lo;
        split2(v.x, v.y, hi, lo);
        int w = (p >> 3) * 16 + (p & 3) * 4 + ((p >> 2) & 1);
        g_Wf[c * 256 + w]     = hi;         // split 0
        g_Wf[c * 256 + w + 2] = lo;         // split 1
    }
}

// ============================ CSR build ====================================
__global__ void hist_rank_kernel(const int* __restrict__ dst, int e) {
    int i = blockIdx.x * blockDim.x + threadIdx.x;
    if (i < e) g_rank[i] = atomicAdd(&g_deg[dst[i]], 1);
}

__global__ void scan_kernel(int n) {
    const int T = 1024;
    int tid  = threadIdx.x;
    int lane = tid & 31;
    int wid  = tid >> 5;
    int C = (n + T - 1) / T;
    int s = tid * C;
    int e = min(s + C, n);

    int sum = 0;
    for (int i = s; i < e; i++) sum += g_deg[i];

    int v = sum;
    #pragma unroll
    for (int d = 1; d < 32; d <<= 1) {
        int t = __shfl_up_sync(0xffffffffu, v, d);
        if (lane >= d) v += t;
    }
    __shared__ int wsum[32];
    if (lane == 31) wsum[wid] = v;
    __syncthreads();
    if (wid == 0) {
        int w = wsum[lane];
        #pragma unroll
        for (int d = 1; d < 32; d <<= 1) {
            int t = __shfl_up_sync(0xffffffffu, w, d);
            if (lane >= d) w += t;
        }
        wsum[lane] = w;
    }
    __syncthreads();

    int excl = (v - sum) + (wid > 0 ? wsum[wid - 1] : 0);
    int run = excl;
    for (int i = s; i < e; i++) {
        g_off[i] = run;
        run += g_deg[i];
    }
    if (e == n) g_off[n] = run;
}

__global__ void scatter_kernel(const int* __restrict__ dst, int e) {
    int i = blockIdx.x * blockDim.x + threadIdx.x;
    if (i < e) g_eidx[g_off[dst[i]] + g_rank[i]] = i;
}

// --------------------------- gather kernel ---------------------------------
// One warp per node, 16B per lane, unroll 8 for MLP. h is read-once 410MB:
// __ldcs (evict-first) keeps it from thrashing L2, so eidx/g_Af/x stay
// resident. Output in fragment-major bf16 hi/lo (default store policy:
// we WANT g_Af L2-resident for the GEMM's cp.async reads).
__global__ void __launch_bounds__(256)
gather_kernel(const float4* __restrict__ h4, int n) {
    int node = blockIdx.x * 8 + (threadIdx.x >> 5);
    int lane = threadIdx.x & 31;
    if (node >= n) return;

    int s = g_off[node];
    int e = g_off[node + 1];
    float4 a = make_float4(0.f, 0.f, 0.f, 0.f);
    int j = s;
    for (; j + 8 <= e; j += 8) {
        float4 v[8];
        #pragma unroll
        for (int u = 0; u < 8; u++) {
            int ei = __ldg(g_eidx + j + u);
            v[u] = __ldcs(h4 + (size_t)ei * 32 + lane);
        }
        #pragma unroll
        for (int u = 0; u < 8; u++) {
            a.x += v[u].x; a.y += v[u].y; a.z += v[u].z; a.w += v[u].w;
        }
    }
    if (j + 4 <= e) {
        float4 v[4];
        #pragma unroll
        for (int u = 0; u < 4; u++) {
            int ei = __ldg(g_eidx + j + u);
            v[u] = __ldcs(h4 + (size_t)ei * 32 + lane);
        }
        #pragma unroll
        for (int u = 0; u < 4; u++) {
            a.x += v[u].x; a.y += v[u].y; a.z += v[u].z; a.w += v[u].w;
        }
        j += 4;
    }
    for (; j < e; j++) {
        int ei = __ldg(g_eidx + j);
        float4 v0 = __ldcs(h4 + (size_t)ei * 32 + lane);
        a.x += v0.x; a.y += v0.y; a.z += v0.z; a.w += v0.w;
    }

    // fragment-major store: pairs p0 = 2*lane, p1 = 2*lane+1 (k = 4*lane..+3)
    uint32_t h0, l0, h1, l1;
    split2(a.x, a.y, h0, l0);
    split2(a.z, a.w, h1, l1);
    size_t base = (size_t)node * 128;
    int p0    = 2 * lane;
    int chunk = p0 >> 5;
    int pp    = p0 & 31;
    int w0 = chunk * 64 + (pp >> 3) * 16 + (pp & 3) * 4 + ((pp >> 2) & 1);
    int w1 = w0 + 4;                        // pair p0+1: tig+1
    g_Af[base + w0]     = h0;
    g_Af[base + w0 + 2] = l0;
    g_Af[base + w1]     = h1;
    g_Af[base + w1 + 2] = l1;
}

// ===================== HMMA GEMM: out = relu(q @ W^T + b) ==================
// CTA = 64 nodes x 128 cols, 256 threads (8 warps: 2m x 4n, warp 32x32).
// K=256 in 4 chunks of 64. Fragment-major smem: per (row, k16 step s, tig)
// the 4 words {hi_k0, hi_k8, lo_k0, lo_k8} are one aligned LDS.128.
// Row stride 80 words -> phase-conflict-free (validated R12).
// W chunks and aggr-A chunks staged via cp.async; x read with __ldcs
// (read-once), out stored with __stcs (write-once). 2 CTAs/SM (R12 shape).
// Split-precision: D += Ah*Wh + Ah*Wl + Al*Wh (fp32 accum).

#define GM       64
#define RW       80
#define SA_W     (GM * RW)                 // 5120 words
#define SW_W     (EMB * RW)                // 10240 words
#define GSMEM_W  (SA_W + SW_W + EMB)
#define GSMEM_B  (GSMEM_W * 4)             // 61952 B

__device__ __forceinline__ void mma_bf16(float4& d,
    uint32_t a0, uint32_t a1, uint32_t a2, uint32_t a3,
    uint32_t b0, uint32_t b1) {
    asm("mma.sync.aligned.m16n8k16.row.col.f32.bf16.bf16.f32 "
        "{%0,%1,%2,%3}, {%4,%5,%6,%7}, {%8,%9}, {%0,%1,%2,%3};"
        : "+f"(d.x), "+f"(d.y), "+f"(d.z), "+f"(d.w)
        : "r"(a0), "r"(a1), "r"(a2), "r"(a3), "r"(b0), "r"(b1));
}

__global__ void __launch_bounds__(256, 2)
gemm_kernel(const float4* __restrict__ x4,
            const float*  __restrict__ bias,
            float* __restrict__ out, int n) {
    extern __shared__ uint32_t sm[];
    uint32_t* sA = sm;                     // [64][80]
    uint32_t* sW = sm + SA_W;              // [128][80]
    float*    sB = reinterpret_cast<float*>(sm + SA_W + SW_W);

    uint32_t sA_u = (uint32_t)__cvta_generic_to_shared(sA);
    uint32_t sW_u = (uint32_t)__cvta_generic_to_shared(sW);

    int tid  = threadIdx.x;
    int warp = tid >> 5;
    int lane = tid & 31;
    int g    = lane >> 2;
    int tig  = lane & 3;
    int mw   = warp >> 2;
    int nw   = warp & 3;
    int m0   = mw * 32;
    int n0   = nw * 32;
    int nb   = blockIdx.x * GM;

    if (tid < EMB) sB[tid] = bias[tid];

    float4 acc[2][4];
    #pragma unroll
    for (int mt = 0; mt < 2; mt++)
        #pragma unroll
        for (int nt = 0; nt < 4; nt++)
            acc[mt][nt] = make_float4(0.f, 0.f, 0.f, 0.f);

    for (int kc = 0; kc < KTOT; kc += 64) {
        __syncthreads();
        // ---- stage W chunk via cp.async: 2048 16B units, 8 per thread ----
        #pragma unroll
        for (int f = tid; f < EMB * 16; f += 256) {
            int c = f >> 4;
            int i = f & 15;
            cp16(sW_u + (c * RW + i * 4) * 4, g_Wf + c * 256 + kc + i * 4);
        }
        if (kc < 128) {
            CP_COMMIT();
            // ---- stage A from x: f32 -> bf16 hi/lo (overlaps cp.async) ----
            #pragma unroll
            for (int f = tid; f < GM * 16; f += 256) {
                int m = f >> 4;
                int q = f & 15;             // float4 = pairs 2q, 2q+1
                int node = nb + m;
                float4 v = make_float4(0.f, 0.f, 0.f, 0.f);
                if (node < n) v = __ldcs(x4 + (size_t)node * 32 + (kc >> 2) + q);
                uint32_t h0, l0, h1, l1;
                split2(v.x, v.y, h0, l0);
                split2(v.z, v.w, h1, l1);
                int p0 = 2 * q;
                int w0 = (p0 >> 3) * 16 + (p0 & 3) * 4 + ((p0 >> 2) & 1);
                int rb = m * RW;
                sA[rb + w0]         = h0;
                sA[rb + w0 + 2]     = l0;
                sA[rb + w0 + 4]     = h1;   // pair p0+1: tig+1
                sA[rb + w0 + 6]     = l1;
            }
        } else {
            // ---- stage A from fragment-major aggr via cp.async ----
            // (g_Af padded past N_MAX: unguarded reads OK; rows >= n
            //  carry garbage but are never stored in the epilogue)
            int cb = (kc - 128);            // 0 or 64: word base in g_Af
            #pragma unroll
            for (int f = tid; f < GM * 16; f += 256) {
                int m = f >> 4;
                int i = f & 15;
                cp16(sA_u + (m * RW + i * 4) * 4,
                     g_Af + (size_t)(nb + m) * 128 + cb + i * 4);
            }
            CP_COMMIT();
        }
        CP_WAIT0();
        __syncthreads();

        // ---- 4 k16 steps, 8 LDS.128 each ----
        #pragma unroll
        for (int s = 0; s < 4; s++) {
            int wb = s * 16 + tig * 4;

            uint4 A0[2], A1[2];             // {h_k0, h_k8, l_k0, l_k8}
            #pragma unroll
            for (int mt = 0; mt < 2; mt++) {
                int r0 = (m0 + mt * 16 + g) * RW + wb;
                A0[mt] = *reinterpret_cast<const uint4*>(sA + r0);
                A1[mt] = *reinterpret_cast<const uint4*>(sA + r0 + 8 * RW);
            }
            uint4 B[4];                     // {bh0, bh1, bl0, bl1}
            #pragma unroll
            for (int nt = 0; nt < 4; nt++) {
                int rn = (n0 + nt * 8 + g) * RW + wb;
                B[nt] = *reinterpret_cast<const uint4*>(sW + rn);
            }
            #pragma unroll
            for (int mt = 0; mt < 2; mt++)
                #pragma unroll
                for (int nt = 0; nt < 4; nt++) {
                    mma_bf16(acc[mt][nt],
                             A0[mt].x, A1[mt].x, A0[mt].y, A1[mt].y,
                             B[nt].x, B[nt].y);
                    mma_bf16(acc[mt][nt],
                             A0[mt].x, A1[mt].x, A0[mt].y, A1[mt].y,
                             B[nt].z, B[nt].w);
                    mma_bf16(acc[mt][nt],
                             A0[mt].z, A1[mt].z, A0[mt].w, A1[mt].w,
                             B[nt].x, B[nt].y);
                }
        }
    }

    // ---- epilogue: bias + relu + streaming store ----
    #pragma unroll
    for (int mt = 0; mt < 2; mt++) {
        int r0 = nb + m0 + mt * 16 + g;
        int r1 = r0 + 8;
        #pragma unroll
        for (int nt = 0; nt < 4; nt++) {
            int col = n0 + nt * 8 + tig * 2;
            float bx = sB[col], by = sB[col + 1];
            float4 a = acc[mt][nt];
            if (r0 < n) {
                float2 v = make_float2(fmaxf(a.x + bx, 0.f),
                                       fmaxf(a.y + by, 0.f));
                __stcs(reinterpret_cast<float2*>(out + (size_t)r0 * EMB + col), v);
            }
            if (r1 < n) {
                float2 v = make_float2(fmaxf(a.z + bx, 0.f),
                                       fmaxf(a.w + by, 0.f));
                __stcs(reinterpret_cast<float2*>(out + (size_t)r1 * EMB + col), v);
            }
        }
    }
}

// ---------------- launch ----------------------------------------------------
extern "C" void kernel_launch(void* const* d_in, const int* in_sizes, int n_in,
                              void* d_out, int out_size) {
    const float* h        = (const float*)d_in[0];   // [E, 128]
    const float* x        = (const float*)d_in[1];   // [N, 128]
    const int*   edge_dst = (const int*)  d_in[2];   // [E] int32
    const float* W        = (const float*)d_in[3];   // [128, 256]
    const float* b        = (const float*)d_in[4];   // [128]
    float*       out      = (float*)d_out;           // [N, 128]

    int E = in_sizes[2];
    int N = in_sizes[1] / EMB;

    cudaFuncSetAttribute(gemm_kernel,
                         cudaFuncAttributeMaxDynamicSharedMemorySize, GSMEM_B);

    int prepN = (N > EMB * (KTOT / 2)) ? N : EMB * (KTOT / 2);

    prep_kernel<<<(prepN + 255) / 256, 256>>>(
        reinterpret_cast<const float2*>(W), N);
    hist_rank_kernel<<<(E + 255) / 256, 256>>>(edge_dst, E);
    scan_kernel<<<1, 1024>>>(N);
    scatter_kernel<<<(E + 255) / 256, 256>>>(edge_dst, E);
    gather_kernel<<<(N + 7) / 8, 256>>>(
        reinterpret_cast<const float4*>(h), N);
    gemm_kernel<<<(N + GM - 1) / GM, 256, GSMEM_B>>>(
        reinterpret_cast<const float4*>(x), b, out, N);
}